// round 11
// baseline (speedup 1.0000x reference)
#include <cuda_runtime.h>
#include <cuda_fp16.h>
#include <cstdint>
#include <float.h>
#include <math.h>

#define DIMD   4096
#define NEXP   256
#define TOPK   8
#define MAXT   16384
#define KCH    32
#define NCHUNK (DIMD / KCH)   // 128

// Device-global scratch (allocation-free per harness rules)
__device__ float g_logits[MAXT * NEXP];            // 16 MB
__device__ uint4 g_wfrag[2 * NCHUNK * 2 * 16 * 32];// 4 MB: W split hi/lo fp16, B-fragment order
__device__ float4 g_wq[NEXP * (DIMD / 4)];         // 4 MB: W transposed k-major (repair path)
__device__ int   g_risky[MAXT];
__device__ int   g_risky_count;

#define TAU 1e-5f   // decision-margin threshold (noise ~1e-6 -> ~10x safety; proven R8)

// ---------------------------------------------------------------------------
__device__ __forceinline__ uint32_t smem_u32(const void* p) {
    uint32_t a;
    asm("{ .reg .u64 t; cvta.to.shared.u64 t, %1; cvt.u32.u64 %0, t; }" : "=r"(a) : "l"(p));
    return a;
}
__device__ __forceinline__ void cpasync16(uint32_t dst, const void* src) {
    asm volatile("cp.async.cg.shared.global [%0], [%1], 16;" :: "r"(dst), "l"(src));
}
__device__ __forceinline__ uint32_t pack_h2(__half a, __half b) {
    __half2 p = __halves2half2(a, b);
    return *reinterpret_cast<uint32_t*>(&p);
}
__device__ __forceinline__ void mma_f16(float* d, const uint32_t* a, const uint32_t* b) {
    asm volatile(
        "mma.sync.aligned.m16n8k16.row.col.f32.f16.f16.f32 "
        "{%0,%1,%2,%3}, {%4,%5,%6,%7}, {%8,%9}, {%0,%1,%2,%3};"
        : "+f"(d[0]), "+f"(d[1]), "+f"(d[2]), "+f"(d[3])
        : "r"(a[0]), "r"(a[1]), "r"(a[2]), "r"(a[3]), "r"(b[0]), "r"(b[1]));
}
__device__ __forceinline__ void mma_f16_z(float* d, const uint32_t* a, const uint32_t* b) {
    asm volatile(
        "mma.sync.aligned.m16n8k16.row.col.f32.f16.f16.f32 "
        "{%0,%1,%2,%3}, {%4,%5,%6,%7}, {%8,%9}, {%10,%11,%12,%13};"
        : "=f"(d[0]), "=f"(d[1]), "=f"(d[2]), "=f"(d[3])
        : "r"(a[0]), "r"(a[1]), "r"(a[2]), "r"(a[3]), "r"(b[0]), "r"(b[1]),
          "f"(0.f), "f"(0.f), "f"(0.f), "f"(0.f));
}
__device__ __forceinline__ void ldsm4(uint32_t* r, uint32_t addr) {
    asm volatile("ldmatrix.sync.aligned.m8n8.x4.shared.b16 {%0,%1,%2,%3}, [%4];"
        : "=r"(r[0]), "=r"(r[1]), "=r"(r[2]), "=r"(r[3]) : "r"(addr));
}

// SMEM layout (bytes): per stage A-hi 8K, A-lo 8K, B 16K. 2 stages = 64 KB.
#define SM_AHI(s) ((s) * 16384)
#define SM_ALO(s) ((s) * 16384 + 8192)
#define SM_B(s)   (32768 + (s) * 16384)
#define SM_TOTAL  65536

// ---------------------------------------------------------------------------
// Prep (single launch): W -> fp16 hi/lo fragments (GEMM) + k-major fp32 copy
// (repair). Also zeroes the risky counter.
// ---------------------------------------------------------------------------
__global__ void prep_w_kernel(const float* __restrict__ W) {
    if (blockIdx.x == 0 && threadIdx.x == 0) g_risky_count = 0;
    int F = blockIdx.x * blockDim.x + threadIdx.x;   // 0..262143

    {   // task 1: fragment split (B-fragment order, W*4096 hi/lo fp16)
        int lane = F & 31;
        int nt   = (F >> 5) & 15;
        int kk   = (F >> 9) & 1;
        int c    = (F >> 10) & 127;
        int nblk = F >> 17;
        int n  = nblk * 128 + nt * 8 + (lane >> 2);
        int k0 = c * 32 + kk * 16 + (lane & 3) * 2;
        const float* wr = W + (size_t)n * DIMD;
        float2 w01 = *(const float2*)(wr + k0);
        float2 w89 = *(const float2*)(wr + k0 + 8);
        float f0 = w01.x * 4096.f, f1 = w01.y * 4096.f;
        float f2 = w89.x * 4096.f, f3 = w89.y * 4096.f;
        __half h0 = __float2half_rn(f0), h1 = __float2half_rn(f1);
        __half h2 = __float2half_rn(f2), h3 = __float2half_rn(f3);
        __half l0 = __float2half_rn(f0 - __half2float(h0));
        __half l1 = __float2half_rn(f1 - __half2float(h1));
        __half l2 = __float2half_rn(f2 - __half2float(h2));
        __half l3 = __float2half_rn(f3 - __half2float(h3));
        uint4 o;
        o.x = pack_h2(h0, h1); o.y = pack_h2(h2, h3);
        o.z = pack_h2(l0, l1); o.w = pack_h2(l2, l3);
        g_wfrag[F] = o;
    }

    {   // task 2: k-major transpose for repair
        int e  = F & 255;
        int k4 = F >> 8;
        g_wq[F] = *(const float4*)(W + (size_t)e * DIMD + k4 * 4);
    }
}

// ---------------------------------------------------------------------------
// 3x-fp16 GEMM via mma.m16n8k16 — exact R6 configuration (measured ~340 us).
// ---------------------------------------------------------------------------
__global__ void __launch_bounds__(256, 1)
gate_gemm_f16(const float* __restrict__ X)
{
    extern __shared__ char smem[];
    const uint32_t sb = smem_u32(smem);
    const int tid  = threadIdx.x;
    const int lane = tid & 31;
    const int wid  = tid >> 5;
    const int nblk = blockIdx.x;
    const int n0   = nblk * 128;
    const int m0   = blockIdx.y * 128;

    const int wm = wid & 1;
    const int wn = wid >> 1;

    float acc[4][4][4];
#pragma unroll
    for (int i = 0; i < 4; i++)
#pragma unroll
        for (int j = 0; j < 4; j++)
#pragma unroll
            for (int r = 0; r < 4; r++) acc[i][j][r] = 0.f;

    float4 xr[4];
    auto ldX = [&](int c) {
#pragma unroll
        for (int u = 0; u < 4; u++) {
            int q = tid + u * 256;
            int m = q >> 3, c4 = q & 7;
            xr[u] = *(const float4*)(X + (size_t)(m0 + m) * DIMD + c * KCH + c4 * 4);
        }
    };
    auto stsA = [&](int s) {
#pragma unroll
        for (int u = 0; u < 4; u++) {
            int q = tid + u * 256;
            int m = q >> 3, c4 = q & 7;
            float v[4] = {xr[u].x, xr[u].y, xr[u].z, xr[u].w};
            __half h[4], l[4];
#pragma unroll
            for (int e = 0; e < 4; e++) {
                h[e] = __float2half_rn(v[e]);
                l[e] = __float2half_rn(v[e] - __half2float(h[e]));
            }
            uint32_t off = m * 64 + ((((c4 >> 1) ^ ((m >> 1) & 3)) << 4)) + ((c4 & 1) << 3);
            *(uint2*)(smem + SM_AHI(s) + off) = make_uint2(pack_h2(h[0], h[1]), pack_h2(h[2], h[3]));
            *(uint2*)(smem + SM_ALO(s) + off) = make_uint2(pack_h2(l[0], l[1]), pack_h2(l[2], l[3]));
        }
    };
    auto cpB = [&](int c, int s) {
        const uint4* src = g_wfrag + ((size_t)nblk * NCHUNK + c) * 1024;
        uint32_t dst = sb + SM_B(s);
#pragma unroll
        for (int u = 0; u < 4; u++) {
            int q = tid + u * 256;
            cpasync16(dst + q * 16, src + q);
        }
    };
    auto compute = [&](int s) {
        const int r15  = lane & 15;
        const int koff = lane >> 4;
        const int xorv = (r15 >> 1) & 3;
#pragma unroll
        for (int kk = 0; kk < 2; kk++) {
            uint32_t ah[4][4], al[4][4];
#pragma unroll
            for (int i = 0; i < 4; i++) {
                int row = wm * 64 + i * 16 + r15;
                uint32_t off = row * 64 + ((((kk * 2 + koff) ^ xorv)) << 4);
                ldsm4(ah[i], sb + SM_AHI(s) + off);
                ldsm4(al[i], sb + SM_ALO(s) + off);
            }
            uint4 bf[4];
#pragma unroll
            for (int j = 0; j < 4; j++) {
                int nt = wn * 4 + j;
                bf[j] = *(const uint4*)(smem + SM_B(s) + ((kk * 16 + nt) * 32 + lane) * 16);
            }
#pragma unroll
            for (int i = 0; i < 4; i++) {
#pragma unroll
                for (int j = 0; j < 4; j++) {
                    uint32_t bh[2] = {bf[j].x, bf[j].y};
                    uint32_t bl[2] = {bf[j].z, bf[j].w};
                    float dt[4];
                    mma_f16_z(dt, ah[i], bh);
                    mma_f16(dt, ah[i], bl);
                    mma_f16(dt, al[i], bh);
                    acc[i][j][0] += dt[0];
                    acc[i][j][1] += dt[1];
                    acc[i][j][2] += dt[2];
                    acc[i][j][3] += dt[3];
                }
            }
        }
    };

    ldX(0);
    cpB(0, 0);
    asm volatile("cp.async.commit_group;" ::: "memory");
    stsA(0);
    ldX(1);
    __syncthreads();

    for (int c = 0; c < NCHUNK; c++) {
        const int s = c & 1;
        asm volatile("cp.async.wait_group 0;" ::: "memory");
        __syncthreads();
        if (c + 1 < NCHUNK) {
            cpB(c + 1, s ^ 1);
            asm volatile("cp.async.commit_group;" ::: "memory");
            stsA(s ^ 1);
            if (c + 2 < NCHUNK) ldX(c + 2);
        }
        compute(s);
    }

    const float SCL = 1.f / 4096.f;
#pragma unroll
    for (int i = 0; i < 4; i++) {
        int row0 = m0 + wm * 64 + i * 16 + (lane >> 2);
#pragma unroll
        for (int j = 0; j < 4; j++) {
            int col = n0 + wn * 32 + j * 8 + (lane & 3) * 2;
            *(float2*)(g_logits + (size_t)row0 * NEXP + col) =
                make_float2(acc[i][j][0] * SCL, acc[i][j][1] * SCL);
            *(float2*)(g_logits + (size_t)(row0 + 8) * NEXP + col) =
                make_float2(acc[i][j][2] * SCL, acc[i][j][3] * SCL);
        }
    }
}

// ---------------------------------------------------------------------------
// Shared routing core. DETECT: measure decision margins, flag risky tokens.
// ---------------------------------------------------------------------------
template <bool DETECT>
__device__ __forceinline__ void route_core(float v[8], int lane, int token,
                                           float* __restrict__ wout,
                                           float* __restrict__ iout, int two_out)
{
    float m = v[0];
#pragma unroll
    for (int j = 1; j < 8; j++) m = fmaxf(m, v[j]);
#pragma unroll
    for (int o = 16; o; o >>= 1) m = fmaxf(m, __shfl_xor_sync(0xffffffffu, m, o));

    float e[8], s = 0.f;
#pragma unroll
    for (int j = 0; j < 8; j++) { e[j] = expf(v[j] - m); s += e[j]; }
#pragma unroll
    for (int o = 16; o; o >>= 1) s += __shfl_xor_sync(0xffffffffu, s, o);
    const float inv = 1.f / s;

    float gm[8];
#pragma unroll
    for (int j = 0; j < 8; j++) {
        float g = v[j];
#pragma unroll
        for (int o = 16; o; o >>= 1) g = fmaxf(g, __shfl_xor_sync(0xffffffffu, g, o));
        gm[j] = g;
    }

    unsigned keep = 0;
    float gv4 = 0.f, gv5 = 0.f;
#pragma unroll
    for (int r = 0; r < 5; r++) {
        int best = -1; float bv = -FLT_MAX;
#pragma unroll
        for (int g = 0; g < 8; g++) {
            if (keep & (1u << g)) continue;
            if (gm[g] > bv) { bv = gm[g]; best = g; }
        }
        if (r < 4) keep |= 1u << best;
        if (r == 3) gv4 = bv;
        if (r == 4) gv5 = bv;
    }
    bool risky = DETECT && (gv4 - gv5 < TAU);

    float mv[8];
#pragma unroll
    for (int j = 0; j < 8; j++) mv[j] = ((keep >> j) & 1u) ? e[j] : -FLT_MAX;

    float prev = 0.f;
#pragma unroll
    for (int r = 0; r < 9; r++) {
        float bv = -FLT_MAX; int bi = NEXP;
#pragma unroll
        for (int j = 0; j < 8; j++) {
            int idx = j * 32 + lane;
            if (mv[j] > bv || (mv[j] == bv && idx < bi)) { bv = mv[j]; bi = idx; }
        }
#pragma unroll
        for (int o = 16; o; o >>= 1) {
            float ov = __shfl_xor_sync(0xffffffffu, bv, o);
            int   oi = __shfl_xor_sync(0xffffffffu, bi, o);
            if (ov > bv || (ov == bv && oi < bi)) { bv = ov; bi = oi; }
        }
        if (DETECT && r > 0 && (prev - bv < TAU * prev)) risky = true;
        prev = bv;
        if (r < 8) {
            if (lane == r) {
                wout[(size_t)token * TOPK + r] = bv * inv;
                if (two_out) iout[(size_t)token * TOPK + r] = (float)bi;
            }
            int jj = bi >> 5, ll = bi & 31;
#pragma unroll
            for (int j = 0; j < 8; j++)
                if (j == jj && lane == ll) mv[j] = -FLT_MAX;
        }
    }

    if (DETECT && risky && lane == 0) {
        int pos = atomicAdd(&g_risky_count, 1);
        g_risky[pos] = token;
    }
}

// ---------------------------------------------------------------------------
__global__ void gate_route_kernel(float* __restrict__ wout,
                                  float* __restrict__ iout,
                                  int T, int two_out)
{
    const int warp = (blockIdx.x * blockDim.x + threadIdx.x) >> 5;
    const int lane = threadIdx.x & 31;
    if (warp >= T) return;
    const float* l = g_logits + (size_t)warp * NEXP;
    float v[8];
#pragma unroll
    for (int j = 0; j < 8; j++) v[j] = l[j * 32 + lane];
    route_core<true>(v, lane, warp, wout, iout, two_out);
}

// ---------------------------------------------------------------------------
// Repair v4: exact ascending-k fmaf chain (serial floor ~65k cyc), with a
// 3-slot ring buffer prefetching 2 blocks (256 chain-cycles) ahead so the
// L2/DRAM latency never stalls the chain.
// ---------------------------------------------------------------------------
#define RB 8   // k4 elements per block; 128 blocks total

__global__ void __launch_bounds__(256)
repair_kernel(const float* __restrict__ X,
              float* __restrict__ wout, float* __restrict__ iout, int two_out)
{
    __shared__ float4 sx[DIMD / 4];   // 16 KB: the token's X row
    __shared__ float  slog[NEXP];

    const int cnt = g_risky_count;
    const int e   = threadIdx.x;

    for (int ti = blockIdx.x; ti < cnt; ti += gridDim.x) {
        const int token = g_risky[ti];

        const float4* xsrc = (const float4*)(X + (size_t)token * DIMD);
#pragma unroll
        for (int u = 0; u < 4; u++)
            sx[e + u * 256] = xsrc[e + u * 256];
        __syncthreads();

        const float4* wq = g_wq + e;
        float4 wb[3][RB];                 // ring: prefetch distance 2 blocks
#pragma unroll
        for (int u = 0; u < RB; u++) wb[0][u] = __ldg(wq + (size_t)u * NEXP);
#pragma unroll
        for (int u = 0; u < RB; u++) wb[1][u] = __ldg(wq + (size_t)(RB + u) * NEXP);

        float a = 0.f;
        const int NB = (DIMD / 4) / RB;   // 128
        for (int kb = 0; kb < NB; kb++) {
            const int cur = kb % 3;
            const int nxt = (kb + 2) % 3;
            if (kb + 2 < NB) {
                const float4* src = wq + (size_t)(kb + 2) * RB * NEXP;
#pragma unroll
                for (int u = 0; u < RB; u++)
                    wb[nxt][u] = __ldg(src + (size_t)u * NEXP);
            }
#pragma unroll
            for (int u = 0; u < RB; u++) {
                float4 w = wb[cur][u];
                float4 x = sx[kb * RB + u];
                a = fmaf(x.x, w.x, a);
                a = fmaf(x.y, w.y, a);
                a = fmaf(x.z, w.z, a);
                a = fmaf(x.w, w.w, a);   // strictly ascending k == R1 chain
            }
        }

        slog[e] = a;
        __syncthreads();
        if (e < 32) {
            float v[8];
#pragma unroll
            for (int j = 0; j < 8; j++) v[j] = slog[j * 32 + e];
            route_core<false>(v, e, token, wout, iout, two_out);
        }
        __syncthreads();
    }
}

// ---------------------------------------------------------------------------
extern "C" void kernel_launch(void* const* d_in, const int* in_sizes, int n_in,
                              void* d_out, int out_size)
{
    const float* X = (const float*)d_in[0];
    const float* W = (const float*)d_in[1];
    const int T = in_sizes[0] / DIMD;   // 16384

    prep_w_kernel<<<1024, 256>>>(W);

    cudaFuncSetAttribute(gate_gemm_f16, cudaFuncAttributeMaxDynamicSharedMemorySize, SM_TOTAL);
    dim3 ggrid(NEXP / 128, T / 128);   // (2, 128) = 256 CTAs, 128x128 tiles
    gate_gemm_f16<<<ggrid, 256, SM_TOTAL>>>(X);

    float* wout = (float*)d_out;
    int two_out = (out_size >= 2 * T * TOPK) ? 1 : 0;
    float* iout = wout + (size_t)T * TOPK;
    gate_route_kernel<<<(T * 32 + 255) / 256, 256>>>(wout, iout, T, two_out);

    repair_kernel<<<256, 256>>>(X, wout, iout, two_out);
}

// round 12
// speedup vs baseline: 1.3494x; 1.3494x over previous
#include <cuda_runtime.h>
#include <cuda_fp16.h>
#include <cstdint>
#include <float.h>
#include <math.h>

#define DIMD   4096
#define NEXP   256
#define TOPK   8
#define MAXT   16384
#define KCH    32
#define NCHUNK (DIMD / KCH)   // 128

// Device-global scratch (allocation-free per harness rules)
__device__ float g_logits[MAXT * NEXP];            // 16 MB
__device__ uint4 g_wfrag[2 * NCHUNK * 2 * 16 * 32];// 4 MB: W split hi/lo fp16, B-fragment order
__device__ float4 g_wq[NEXP * (DIMD / 4)];         // 4 MB: W transposed k-major (repair path)
__device__ int   g_risky[MAXT];
__device__ int   g_risky_count;

#define TAU 1e-5f   // decision-margin threshold (noise ~1e-6 -> ~10x safety; proven R8)

// ---------------------------------------------------------------------------
__device__ __forceinline__ uint32_t smem_u32(const void* p) {
    uint32_t a;
    asm("{ .reg .u64 t; cvta.to.shared.u64 t, %1; cvt.u32.u64 %0, t; }" : "=r"(a) : "l"(p));
    return a;
}
__device__ __forceinline__ void cpasync16(uint32_t dst, const void* src) {
    asm volatile("cp.async.cg.shared.global [%0], [%1], 16;" :: "r"(dst), "l"(src));
}
__device__ __forceinline__ uint32_t pack_h2(__half a, __half b) {
    __half2 p = __halves2half2(a, b);
    return *reinterpret_cast<uint32_t*>(&p);
}
__device__ __forceinline__ void mma_f16(float* d, const uint32_t* a, const uint32_t* b) {
    asm volatile(
        "mma.sync.aligned.m16n8k16.row.col.f32.f16.f16.f32 "
        "{%0,%1,%2,%3}, {%4,%5,%6,%7}, {%8,%9}, {%0,%1,%2,%3};"
        : "+f"(d[0]), "+f"(d[1]), "+f"(d[2]), "+f"(d[3])
        : "r"(a[0]), "r"(a[1]), "r"(a[2]), "r"(a[3]), "r"(b[0]), "r"(b[1]));
}
__device__ __forceinline__ void mma_f16_z(float* d, const uint32_t* a, const uint32_t* b) {
    asm volatile(
        "mma.sync.aligned.m16n8k16.row.col.f32.f16.f16.f32 "
        "{%0,%1,%2,%3}, {%4,%5,%6,%7}, {%8,%9}, {%10,%11,%12,%13};"
        : "=f"(d[0]), "=f"(d[1]), "=f"(d[2]), "=f"(d[3])
        : "r"(a[0]), "r"(a[1]), "r"(a[2]), "r"(a[3]), "r"(b[0]), "r"(b[1]),
          "f"(0.f), "f"(0.f), "f"(0.f), "f"(0.f));
}
__device__ __forceinline__ void ldsm4(uint32_t* r, uint32_t addr) {
    asm volatile("ldmatrix.sync.aligned.m8n8.x4.shared.b16 {%0,%1,%2,%3}, [%4];"
        : "=r"(r[0]), "=r"(r[1]), "=r"(r[2]), "=r"(r[3]) : "r"(addr));
}

// GEMM SMEM layout (bytes): per stage A-hi 8K, A-lo 8K, B 16K. 2 stages = 64 KB.
#define SM_AHI(s) ((s) * 16384)
#define SM_ALO(s) ((s) * 16384 + 8192)
#define SM_B(s)   (32768 + (s) * 16384)
#define SM_TOTAL  65536

// ---------------------------------------------------------------------------
// Prep (single launch): W -> fp16 hi/lo fragments (GEMM) + k-major fp32 copy
// (repair). Also zeroes the risky counter.
// ---------------------------------------------------------------------------
__global__ void prep_w_kernel(const float* __restrict__ W) {
    if (blockIdx.x == 0 && threadIdx.x == 0) g_risky_count = 0;
    int F = blockIdx.x * blockDim.x + threadIdx.x;   // 0..262143

    {   // task 1: fragment split (B-fragment order, W*4096 hi/lo fp16)
        int lane = F & 31;
        int nt   = (F >> 5) & 15;
        int kk   = (F >> 9) & 1;
        int c    = (F >> 10) & 127;
        int nblk = F >> 17;
        int n  = nblk * 128 + nt * 8 + (lane >> 2);
        int k0 = c * 32 + kk * 16 + (lane & 3) * 2;
        const float* wr = W + (size_t)n * DIMD;
        float2 w01 = *(const float2*)(wr + k0);
        float2 w89 = *(const float2*)(wr + k0 + 8);
        float f0 = w01.x * 4096.f, f1 = w01.y * 4096.f;
        float f2 = w89.x * 4096.f, f3 = w89.y * 4096.f;
        __half h0 = __float2half_rn(f0), h1 = __float2half_rn(f1);
        __half h2 = __float2half_rn(f2), h3 = __float2half_rn(f3);
        __half l0 = __float2half_rn(f0 - __half2float(h0));
        __half l1 = __float2half_rn(f1 - __half2float(h1));
        __half l2 = __float2half_rn(f2 - __half2float(h2));
        __half l3 = __float2half_rn(f3 - __half2float(h3));
        uint4 o;
        o.x = pack_h2(h0, h1); o.y = pack_h2(h2, h3);
        o.z = pack_h2(l0, l1); o.w = pack_h2(l2, l3);
        g_wfrag[F] = o;
    }

    {   // task 2: k-major transpose for repair
        int e  = F & 255;
        int k4 = F >> 8;
        g_wq[F] = *(const float4*)(W + (size_t)e * DIMD + k4 * 4);
    }
}

// ---------------------------------------------------------------------------
// 3x-fp16 GEMM via mma.m16n8k16 — exact R6 configuration (measured ~340 us).
// ---------------------------------------------------------------------------
__global__ void __launch_bounds__(256, 1)
gate_gemm_f16(const float* __restrict__ X)
{
    extern __shared__ char smem[];
    const uint32_t sb = smem_u32(smem);
    const int tid  = threadIdx.x;
    const int lane = tid & 31;
    const int wid  = tid >> 5;
    const int nblk = blockIdx.x;
    const int n0   = nblk * 128;
    const int m0   = blockIdx.y * 128;

    const int wm = wid & 1;
    const int wn = wid >> 1;

    float acc[4][4][4];
#pragma unroll
    for (int i = 0; i < 4; i++)
#pragma unroll
        for (int j = 0; j < 4; j++)
#pragma unroll
            for (int r = 0; r < 4; r++) acc[i][j][r] = 0.f;

    float4 xr[4];
    auto ldX = [&](int c) {
#pragma unroll
        for (int u = 0; u < 4; u++) {
            int q = tid + u * 256;
            int m = q >> 3, c4 = q & 7;
            xr[u] = *(const float4*)(X + (size_t)(m0 + m) * DIMD + c * KCH + c4 * 4);
        }
    };
    auto stsA = [&](int s) {
#pragma unroll
        for (int u = 0; u < 4; u++) {
            int q = tid + u * 256;
            int m = q >> 3, c4 = q & 7;
            float v[4] = {xr[u].x, xr[u].y, xr[u].z, xr[u].w};
            __half h[4], l[4];
#pragma unroll
            for (int e = 0; e < 4; e++) {
                h[e] = __float2half_rn(v[e]);
                l[e] = __float2half_rn(v[e] - __half2float(h[e]));
            }
            uint32_t off = m * 64 + ((((c4 >> 1) ^ ((m >> 1) & 3)) << 4)) + ((c4 & 1) << 3);
            *(uint2*)(smem + SM_AHI(s) + off) = make_uint2(pack_h2(h[0], h[1]), pack_h2(h[2], h[3]));
            *(uint2*)(smem + SM_ALO(s) + off) = make_uint2(pack_h2(l[0], l[1]), pack_h2(l[2], l[3]));
        }
    };
    auto cpB = [&](int c, int s) {
        const uint4* src = g_wfrag + ((size_t)nblk * NCHUNK + c) * 1024;
        uint32_t dst = sb + SM_B(s);
#pragma unroll
        for (int u = 0; u < 4; u++) {
            int q = tid + u * 256;
            cpasync16(dst + q * 16, src + q);
        }
    };
    auto compute = [&](int s) {
        const int r15  = lane & 15;
        const int koff = lane >> 4;
        const int xorv = (r15 >> 1) & 3;
#pragma unroll
        for (int kk = 0; kk < 2; kk++) {
            uint32_t ah[4][4], al[4][4];
#pragma unroll
            for (int i = 0; i < 4; i++) {
                int row = wm * 64 + i * 16 + r15;
                uint32_t off = row * 64 + ((((kk * 2 + koff) ^ xorv)) << 4);
                ldsm4(ah[i], sb + SM_AHI(s) + off);
                ldsm4(al[i], sb + SM_ALO(s) + off);
            }
            uint4 bf[4];
#pragma unroll
            for (int j = 0; j < 4; j++) {
                int nt = wn * 4 + j;
                bf[j] = *(const uint4*)(smem + SM_B(s) + ((kk * 16 + nt) * 32 + lane) * 16);
            }
#pragma unroll
            for (int i = 0; i < 4; i++) {
#pragma unroll
                for (int j = 0; j < 4; j++) {
                    uint32_t bh[2] = {bf[j].x, bf[j].y};
                    uint32_t bl[2] = {bf[j].z, bf[j].w};
                    float dt[4];
                    mma_f16_z(dt, ah[i], bh);
                    mma_f16(dt, ah[i], bl);
                    mma_f16(dt, al[i], bh);
                    acc[i][j][0] += dt[0];
                    acc[i][j][1] += dt[1];
                    acc[i][j][2] += dt[2];
                    acc[i][j][3] += dt[3];
                }
            }
        }
    };

    ldX(0);
    cpB(0, 0);
    asm volatile("cp.async.commit_group;" ::: "memory");
    stsA(0);
    ldX(1);
    __syncthreads();

    for (int c = 0; c < NCHUNK; c++) {
        const int s = c & 1;
        asm volatile("cp.async.wait_group 0;" ::: "memory");
        __syncthreads();
        if (c + 1 < NCHUNK) {
            cpB(c + 1, s ^ 1);
            asm volatile("cp.async.commit_group;" ::: "memory");
            stsA(s ^ 1);
            if (c + 2 < NCHUNK) ldX(c + 2);
        }
        compute(s);
    }

    const float SCL = 1.f / 4096.f;
#pragma unroll
    for (int i = 0; i < 4; i++) {
        int row0 = m0 + wm * 64 + i * 16 + (lane >> 2);
#pragma unroll
        for (int j = 0; j < 4; j++) {
            int col = n0 + wn * 32 + j * 8 + (lane & 3) * 2;
            *(float2*)(g_logits + (size_t)row0 * NEXP + col) =
                make_float2(acc[i][j][0] * SCL, acc[i][j][1] * SCL);
            *(float2*)(g_logits + (size_t)(row0 + 8) * NEXP + col) =
                make_float2(acc[i][j][2] * SCL, acc[i][j][3] * SCL);
        }
    }
}

// ---------------------------------------------------------------------------
// Shared routing core. DETECT: measure decision margins, flag risky tokens.
// ---------------------------------------------------------------------------
template <bool DETECT>
__device__ __forceinline__ void route_core(float v[8], int lane, int token,
                                           float* __restrict__ wout,
                                           float* __restrict__ iout, int two_out)
{
    float m = v[0];
#pragma unroll
    for (int j = 1; j < 8; j++) m = fmaxf(m, v[j]);
#pragma unroll
    for (int o = 16; o; o >>= 1) m = fmaxf(m, __shfl_xor_sync(0xffffffffu, m, o));

    float e[8], s = 0.f;
#pragma unroll
    for (int j = 0; j < 8; j++) { e[j] = expf(v[j] - m); s += e[j]; }
#pragma unroll
    for (int o = 16; o; o >>= 1) s += __shfl_xor_sync(0xffffffffu, s, o);
    const float inv = 1.f / s;

    float gm[8];
#pragma unroll
    for (int j = 0; j < 8; j++) {
        float g = v[j];
#pragma unroll
        for (int o = 16; o; o >>= 1) g = fmaxf(g, __shfl_xor_sync(0xffffffffu, g, o));
        gm[j] = g;
    }

    unsigned keep = 0;
    float gv4 = 0.f, gv5 = 0.f;
#pragma unroll
    for (int r = 0; r < 5; r++) {
        int best = -1; float bv = -FLT_MAX;
#pragma unroll
        for (int g = 0; g < 8; g++) {
            if (keep & (1u << g)) continue;
            if (gm[g] > bv) { bv = gm[g]; best = g; }
        }
        if (r < 4) keep |= 1u << best;
        if (r == 3) gv4 = bv;
        if (r == 4) gv5 = bv;
    }
    bool risky = DETECT && (gv4 - gv5 < TAU);

    float mv[8];
#pragma unroll
    for (int j = 0; j < 8; j++) mv[j] = ((keep >> j) & 1u) ? e[j] : -FLT_MAX;

    float prev = 0.f;
#pragma unroll
    for (int r = 0; r < 9; r++) {
        float bv = -FLT_MAX; int bi = NEXP;
#pragma unroll
        for (int j = 0; j < 8; j++) {
            int idx = j * 32 + lane;
            if (mv[j] > bv || (mv[j] == bv && idx < bi)) { bv = mv[j]; bi = idx; }
        }
#pragma unroll
        for (int o = 16; o; o >>= 1) {
            float ov = __shfl_xor_sync(0xffffffffu, bv, o);
            int   oi = __shfl_xor_sync(0xffffffffu, bi, o);
            if (ov > bv || (ov == bv && oi < bi)) { bv = ov; bi = oi; }
        }
        if (DETECT && r > 0 && (prev - bv < TAU * prev)) risky = true;
        prev = bv;
        if (r < 8) {
            if (lane == r) {
                wout[(size_t)token * TOPK + r] = bv * inv;
                if (two_out) iout[(size_t)token * TOPK + r] = (float)bi;
            }
            int jj = bi >> 5, ll = bi & 31;
#pragma unroll
            for (int j = 0; j < 8; j++)
                if (j == jj && lane == ll) mv[j] = -FLT_MAX;
        }
    }

    if (DETECT && risky && lane == 0) {
        int pos = atomicAdd(&g_risky_count, 1);
        g_risky[pos] = token;
    }
}

// ---------------------------------------------------------------------------
__global__ void gate_route_kernel(float* __restrict__ wout,
                                  float* __restrict__ iout,
                                  int T, int two_out)
{
    const int warp = (blockIdx.x * blockDim.x + threadIdx.x) >> 5;
    const int lane = threadIdx.x & 31;
    if (warp >= T) return;
    const float* l = g_logits + (size_t)warp * NEXP;
    float v[8];
#pragma unroll
    for (int j = 0; j < 8; j++) v[j] = l[j * 32 + lane];
    route_core<true>(v, lane, warp, wout, iout, two_out);
}

// ---------------------------------------------------------------------------
// Repair v5: exact ascending-k fmaf chain, W prefetched through a 3-stage
// SMEM ring via cp.async. Thread e writes AND reads only column e, so
// completion is per-thread (cp.async.wait_group) — no barriers, no register
// ring (v4's spill), prefetch distance = 2 blocks = 512 chain-cycles.
// ---------------------------------------------------------------------------
#define RB      16                     // k4 per block
#define RNB     ((DIMD / 4) / RB)      // 64 blocks
#define RSTG    3
// dynamic smem: sx float4[1024] | sw float4[RSTG*RB*256] | slog float[256]
#define RSM_SX    0
#define RSM_SW    (1024 * 16)
#define RSM_SLOG  (RSM_SW + RSTG * RB * 256 * 16)
#define RSM_SIZE  (RSM_SLOG + 256 * 4)   // 213.3 KB

__global__ void __launch_bounds__(256)
repair_kernel(const float* __restrict__ X,
              float* __restrict__ wout, float* __restrict__ iout, int two_out)
{
    extern __shared__ char rsm[];
    float4* sx   = (float4*)(rsm + RSM_SX);
    float*  slog = (float*)(rsm + RSM_SLOG);
    const uint32_t swb = smem_u32(rsm + RSM_SW);

    const int cnt = g_risky_count;
    const int e   = threadIdx.x;

    // issue one block's worth of W prefetch into stage s
    auto cpW = [&](int kb, int s) {
        const float4* src = g_wq + (size_t)kb * RB * NEXP + e;
        uint32_t dst = swb + ((s * RB) * 256 + e) * 16;
#pragma unroll
        for (int u = 0; u < RB; u++)
            cpasync16(dst + u * 256 * 16, src + (size_t)u * NEXP);
        asm volatile("cp.async.commit_group;" ::: "memory");
    };

    for (int ti = blockIdx.x; ti < cnt; ti += gridDim.x) {
        const int token = g_risky[ti];

        const float4* xsrc = (const float4*)(X + (size_t)token * DIMD);
#pragma unroll
        for (int u = 0; u < 4; u++)
            sx[e + u * 256] = xsrc[e + u * 256];

        cpW(0, 0);
        cpW(1, 1);

        float a = 0.f;
        for (int kb = 0; kb < RNB; kb++) {
            const int s = kb % RSTG;
            if (kb + 2 < RNB) {
                cpW(kb + 2, (kb + 2) % RSTG);
                asm volatile("cp.async.wait_group 2;" ::: "memory");
            } else if (kb + 1 < RNB) {
                asm volatile("cp.async.wait_group 1;" ::: "memory");
            } else {
                asm volatile("cp.async.wait_group 0;" ::: "memory");
            }
            const float4* wblk = (float4*)(rsm + RSM_SW) + (s * RB) * 256 + e;
            const float4* xblk = sx + kb * RB;
#pragma unroll
            for (int u = 0; u < RB; u++) {
                float4 w = wblk[u * 256];
                float4 x = xblk[u];
                a = fmaf(x.x, w.x, a);
                a = fmaf(x.y, w.y, a);
                a = fmaf(x.z, w.z, a);
                a = fmaf(x.w, w.w, a);   // strictly ascending k == R1 chain
            }
        }

        slog[e] = a;
        __syncthreads();
        if (e < 32) {
            float v[8];
#pragma unroll
            for (int j = 0; j < 8; j++) v[j] = slog[j * 32 + e];
            route_core<false>(v, e, token, wout, iout, two_out);
        }
        __syncthreads();   // protect slog/sx before next token
    }
}

// ---------------------------------------------------------------------------
extern "C" void kernel_launch(void* const* d_in, const int* in_sizes, int n_in,
                              void* d_out, int out_size)
{
    const float* X = (const float*)d_in[0];
    const float* W = (const float*)d_in[1];
    const int T = in_sizes[0] / DIMD;   // 16384

    prep_w_kernel<<<1024, 256>>>(W);

    cudaFuncSetAttribute(gate_gemm_f16, cudaFuncAttributeMaxDynamicSharedMemorySize, SM_TOTAL);
    dim3 ggrid(NEXP / 128, T / 128);   // (2, 128) = 256 CTAs, 128x128 tiles
    gate_gemm_f16<<<ggrid, 256, SM_TOTAL>>>(X);

    float* wout = (float*)d_out;
    int two_out = (out_size >= 2 * T * TOPK) ? 1 : 0;
    float* iout = wout + (size_t)T * TOPK;
    gate_route_kernel<<<(T * 32 + 255) / 256, 256>>>(wout, iout, T, two_out);

    cudaFuncSetAttribute(repair_kernel, cudaFuncAttributeMaxDynamicSharedMemorySize, RSM_SIZE);
    repair_kernel<<<256, 256, RSM_SIZE>>>(X, wout, iout, two_out);
}

// round 13
// speedup vs baseline: 1.3580x; 1.0064x over previous
#include <cuda_runtime.h>
#include <cuda_fp16.h>
#include <cstdint>
#include <float.h>
#include <math.h>

#define DIMD   4096
#define NEXP   256
#define TOPK   8
#define MAXT   16384
#define KCH    32
#define NCHUNK (DIMD / KCH)   // 128

// Device-global scratch (allocation-free per harness rules)
__device__ float g_logits[MAXT * NEXP];            // 16 MB
__device__ uint4 g_wfrag[2 * NCHUNK * 2 * 16 * 32];// 4 MB: W split hi/lo fp16, B-fragment order
__device__ float4 g_wq[NEXP * (DIMD / 4)];         // 4 MB: W transposed k-major (repair path)
__device__ int   g_risky[MAXT];
__device__ int   g_risky_count;

#define TAU_G    1e-5f   // group-margin threshold (absolute, logits; noise ~1e-6)
#define TAU_RANK 5e-5f   // rank-margin threshold (relative, scores; covers 2^-16 key trunc)

// ---------------------------------------------------------------------------
__device__ __forceinline__ uint32_t smem_u32(const void* p) {
    uint32_t a;
    asm("{ .reg .u64 t; cvta.to.shared.u64 t, %1; cvt.u32.u64 %0, t; }" : "=r"(a) : "l"(p));
    return a;
}
__device__ __forceinline__ void cpasync16(uint32_t dst, const void* src) {
    asm volatile("cp.async.cg.shared.global [%0], [%1], 16;" :: "r"(dst), "l"(src));
}
__device__ __forceinline__ uint32_t pack_h2(__half a, __half b) {
    __half2 p = __halves2half2(a, b);
    return *reinterpret_cast<uint32_t*>(&p);
}
__device__ __forceinline__ void mma_f16(float* d, const uint32_t* a, const uint32_t* b) {
    asm volatile(
        "mma.sync.aligned.m16n8k16.row.col.f32.f16.f16.f32 "
        "{%0,%1,%2,%3}, {%4,%5,%6,%7}, {%8,%9}, {%0,%1,%2,%3};"
        : "+f"(d[0]), "+f"(d[1]), "+f"(d[2]), "+f"(d[3])
        : "r"(a[0]), "r"(a[1]), "r"(a[2]), "r"(a[3]), "r"(b[0]), "r"(b[1]));
}
__device__ __forceinline__ void mma_f16_z(float* d, const uint32_t* a, const uint32_t* b) {
    asm volatile(
        "mma.sync.aligned.m16n8k16.row.col.f32.f16.f16.f32 "
        "{%0,%1,%2,%3}, {%4,%5,%6,%7}, {%8,%9}, {%10,%11,%12,%13};"
        : "=f"(d[0]), "=f"(d[1]), "=f"(d[2]), "=f"(d[3])
        : "r"(a[0]), "r"(a[1]), "r"(a[2]), "r"(a[3]), "r"(b[0]), "r"(b[1]),
          "f"(0.f), "f"(0.f), "f"(0.f), "f"(0.f));
}
__device__ __forceinline__ void ldsm4(uint32_t* r, uint32_t addr) {
    asm volatile("ldmatrix.sync.aligned.m8n8.x4.shared.b16 {%0,%1,%2,%3}, [%4];"
        : "=r"(r[0]), "=r"(r[1]), "=r"(r[2]), "=r"(r[3]) : "r"(addr));
}

// GEMM SMEM layout (bytes): per stage A-hi 8K, A-lo 8K, B 16K. 2 stages = 64 KB.
#define SM_AHI(s) ((s) * 16384)
#define SM_ALO(s) ((s) * 16384 + 8192)
#define SM_B(s)   (32768 + (s) * 16384)
#define SM_TOTAL  65536

// ---------------------------------------------------------------------------
// Prep (single launch): W -> fp16 hi/lo fragments (GEMM) + k-major fp32 copy
// (repair). Also zeroes the risky counter.
// ---------------------------------------------------------------------------
__global__ void prep_w_kernel(const float* __restrict__ W) {
    if (blockIdx.x == 0 && threadIdx.x == 0) g_risky_count = 0;
    int F = blockIdx.x * blockDim.x + threadIdx.x;   // 0..262143

    {   // task 1: fragment split (B-fragment order, W*4096 hi/lo fp16)
        int lane = F & 31;
        int nt   = (F >> 5) & 15;
        int kk   = (F >> 9) & 1;
        int c    = (F >> 10) & 127;
        int nblk = F >> 17;
        int n  = nblk * 128 + nt * 8 + (lane >> 2);
        int k0 = c * 32 + kk * 16 + (lane & 3) * 2;
        const float* wr = W + (size_t)n * DIMD;
        float2 w01 = *(const float2*)(wr + k0);
        float2 w89 = *(const float2*)(wr + k0 + 8);
        float f0 = w01.x * 4096.f, f1 = w01.y * 4096.f;
        float f2 = w89.x * 4096.f, f3 = w89.y * 4096.f;
        __half h0 = __float2half_rn(f0), h1 = __float2half_rn(f1);
        __half h2 = __float2half_rn(f2), h3 = __float2half_rn(f3);
        __half l0 = __float2half_rn(f0 - __half2float(h0));
        __half l1 = __float2half_rn(f1 - __half2float(h1));
        __half l2 = __float2half_rn(f2 - __half2float(h2));
        __half l3 = __float2half_rn(f3 - __half2float(h3));
        uint4 o;
        o.x = pack_h2(h0, h1); o.y = pack_h2(h2, h3);
        o.z = pack_h2(l0, l1); o.w = pack_h2(l2, l3);
        g_wfrag[F] = o;
    }

    {   // task 2: k-major transpose for repair
        int e  = F & 255;
        int k4 = F >> 8;
        g_wq[F] = *(const float4*)(W + (size_t)e * DIMD + k4 * 4);
    }
}

// ---------------------------------------------------------------------------
// 3x-fp16 GEMM via mma.m16n8k16 — exact R6/R10 configuration (~345 us,
// at the measured legacy-HMMA issue floor).
// ---------------------------------------------------------------------------
__global__ void __launch_bounds__(256, 1)
gate_gemm_f16(const float* __restrict__ X)
{
    extern __shared__ char smem[];
    const uint32_t sb = smem_u32(smem);
    const int tid  = threadIdx.x;
    const int lane = tid & 31;
    const int wid  = tid >> 5;
    const int nblk = blockIdx.x;
    const int n0   = nblk * 128;
    const int m0   = blockIdx.y * 128;

    const int wm = wid & 1;
    const int wn = wid >> 1;

    float acc[4][4][4];
#pragma unroll
    for (int i = 0; i < 4; i++)
#pragma unroll
        for (int j = 0; j < 4; j++)
#pragma unroll
            for (int r = 0; r < 4; r++) acc[i][j][r] = 0.f;

    float4 xr[4];
    auto ldX = [&](int c) {
#pragma unroll
        for (int u = 0; u < 4; u++) {
            int q = tid + u * 256;
            int m = q >> 3, c4 = q & 7;
            xr[u] = *(const float4*)(X + (size_t)(m0 + m) * DIMD + c * KCH + c4 * 4);
        }
    };
    auto stsA = [&](int s) {
#pragma unroll
        for (int u = 0; u < 4; u++) {
            int q = tid + u * 256;
            int m = q >> 3, c4 = q & 7;
            float v[4] = {xr[u].x, xr[u].y, xr[u].z, xr[u].w};
            __half h[4], l[4];
#pragma unroll
            for (int e = 0; e < 4; e++) {
                h[e] = __float2half_rn(v[e]);
                l[e] = __float2half_rn(v[e] - __half2float(h[e]));
            }
            uint32_t off = m * 64 + ((((c4 >> 1) ^ ((m >> 1) & 3)) << 4)) + ((c4 & 1) << 3);
            *(uint2*)(smem + SM_AHI(s) + off) = make_uint2(pack_h2(h[0], h[1]), pack_h2(h[2], h[3]));
            *(uint2*)(smem + SM_ALO(s) + off) = make_uint2(pack_h2(l[0], l[1]), pack_h2(l[2], l[3]));
        }
    };
    auto cpB = [&](int c, int s) {
        const uint4* src = g_wfrag + ((size_t)nblk * NCHUNK + c) * 1024;
        uint32_t dst = sb + SM_B(s);
#pragma unroll
        for (int u = 0; u < 4; u++) {
            int q = tid + u * 256;
            cpasync16(dst + q * 16, src + q);
        }
    };
    auto compute = [&](int s) {
        const int r15  = lane & 15;
        const int koff = lane >> 4;
        const int xorv = (r15 >> 1) & 3;
#pragma unroll
        for (int kk = 0; kk < 2; kk++) {
            uint32_t ah[4][4], al[4][4];
#pragma unroll
            for (int i = 0; i < 4; i++) {
                int row = wm * 64 + i * 16 + r15;
                uint32_t off = row * 64 + ((((kk * 2 + koff) ^ xorv)) << 4);
                ldsm4(ah[i], sb + SM_AHI(s) + off);
                ldsm4(al[i], sb + SM_ALO(s) + off);
            }
            uint4 bf[4];
#pragma unroll
            for (int j = 0; j < 4; j++) {
                int nt = wn * 4 + j;
                bf[j] = *(const uint4*)(smem + SM_B(s) + ((kk * 16 + nt) * 32 + lane) * 16);
            }
#pragma unroll
            for (int i = 0; i < 4; i++) {
#pragma unroll
                for (int j = 0; j < 4; j++) {
                    uint32_t bh[2] = {bf[j].x, bf[j].y};
                    uint32_t bl[2] = {bf[j].z, bf[j].w};
                    float dt[4];
                    mma_f16_z(dt, ah[i], bh);
                    mma_f16(dt, ah[i], bl);
                    mma_f16(dt, al[i], bh);
                    acc[i][j][0] += dt[0];
                    acc[i][j][1] += dt[1];
                    acc[i][j][2] += dt[2];
                    acc[i][j][3] += dt[3];
                }
            }
        }
    };

    ldX(0);
    cpB(0, 0);
    asm volatile("cp.async.commit_group;" ::: "memory");
    stsA(0);
    ldX(1);
    __syncthreads();

    for (int c = 0; c < NCHUNK; c++) {
        const int s = c & 1;
        asm volatile("cp.async.wait_group 0;" ::: "memory");
        __syncthreads();
        if (c + 1 < NCHUNK) {
            cpB(c + 1, s ^ 1);
            asm volatile("cp.async.commit_group;" ::: "memory");
            stsA(s ^ 1);
            if (c + 2 < NCHUNK) ldX(c + 2);
        }
        compute(s);
    }

    const float SCL = 1.f / 4096.f;
#pragma unroll
    for (int i = 0; i < 4; i++) {
        int row0 = m0 + wm * 64 + i * 16 + (lane >> 2);
#pragma unroll
        for (int j = 0; j < 4; j++) {
            int col = n0 + wn * 32 + j * 8 + (lane & 3) * 2;
            *(float2*)(g_logits + (size_t)row0 * NEXP + col) =
                make_float2(acc[i][j][0] * SCL, acc[i][j][1] * SCL);
            *(float2*)(g_logits + (size_t)(row0 + 8) * NEXP + col) =
                make_float2(acc[i][j][2] * SCL, acc[i][j][3] * SCL);
        }
    }
}

// ---------------------------------------------------------------------------
// Exact routing core (reference semantics; used by repair). Identical
// arithmetic to R1's validated path.
// ---------------------------------------------------------------------------
__device__ __forceinline__ void route_exact(float v[8], int lane, int token,
                                            float* __restrict__ wout,
                                            float* __restrict__ iout, int two_out)
{
    float m = v[0];
#pragma unroll
    for (int j = 1; j < 8; j++) m = fmaxf(m, v[j]);
#pragma unroll
    for (int o = 16; o; o >>= 1) m = fmaxf(m, __shfl_xor_sync(0xffffffffu, m, o));

    float e[8], s = 0.f;
#pragma unroll
    for (int j = 0; j < 8; j++) { e[j] = expf(v[j] - m); s += e[j]; }
#pragma unroll
    for (int o = 16; o; o >>= 1) s += __shfl_xor_sync(0xffffffffu, s, o);
    const float inv = 1.f / s;

    float gm[8];
#pragma unroll
    for (int j = 0; j < 8; j++) {
        float g = v[j];
#pragma unroll
        for (int o = 16; o; o >>= 1) g = fmaxf(g, __shfl_xor_sync(0xffffffffu, g, o));
        gm[j] = g;
    }

    unsigned keep = 0;
#pragma unroll
    for (int r = 0; r < 4; r++) {
        int best = -1; float bv = -FLT_MAX;
#pragma unroll
        for (int g = 0; g < 8; g++) {
            if (keep & (1u << g)) continue;
            if (gm[g] > bv) { bv = gm[g]; best = g; }
        }
        keep |= 1u << best;
    }

    float mv[8];
#pragma unroll
    for (int j = 0; j < 8; j++) mv[j] = ((keep >> j) & 1u) ? e[j] : -FLT_MAX;

#pragma unroll
    for (int r = 0; r < 8; r++) {
        float bv = -FLT_MAX; int bi = NEXP;
#pragma unroll
        for (int j = 0; j < 8; j++) {
            int idx = j * 32 + lane;
            if (mv[j] > bv || (mv[j] == bv && idx < bi)) { bv = mv[j]; bi = idx; }
        }
#pragma unroll
        for (int o = 16; o; o >>= 1) {
            float ov = __shfl_xor_sync(0xffffffffu, bv, o);
            int   oi = __shfl_xor_sync(0xffffffffu, bi, o);
            if (ov > bv || (ov == bv && oi < bi)) { bv = ov; bi = oi; }
        }
        if (lane == r) {
            wout[(size_t)token * TOPK + r] = bv * inv;
            if (two_out) iout[(size_t)token * TOPK + r] = (float)bi;
        }
        int jj = bi >> 5, ll = bi & 31;
#pragma unroll
        for (int j = 0; j < 8; j++)
            if (j == jj && lane == ll) mv[j] = -FLT_MAX;
    }
}

// ---------------------------------------------------------------------------
// Fast routing with margin detection. Packed-key top-k: key = trunc24(e) |
// (255-idx). Any ordering affected by the 2^-16 truncation is inside the
// TAU_RANK margin and gets flagged risky -> repaired with exact arithmetic.
// ---------------------------------------------------------------------------
__global__ void gate_route_kernel(float* __restrict__ wout,
                                  float* __restrict__ iout,
                                  int T, int two_out)
{
    const int warp = (blockIdx.x * blockDim.x + threadIdx.x) >> 5;
    const int lane = threadIdx.x & 31;
    if (warp >= T) return;
    const float* l = g_logits + (size_t)warp * NEXP;
    float v[8];
#pragma unroll
    for (int j = 0; j < 8; j++) v[j] = l[j * 32 + lane];

    // softmax pieces (exact)
    float m = v[0];
#pragma unroll
    for (int j = 1; j < 8; j++) m = fmaxf(m, v[j]);
#pragma unroll
    for (int o = 16; o; o >>= 1) m = fmaxf(m, __shfl_xor_sync(0xffffffffu, m, o));
    float e[8], s = 0.f;
#pragma unroll
    for (int j = 0; j < 8; j++) { e[j] = expf(v[j] - m); s += e[j]; }
#pragma unroll
    for (int o = 16; o; o >>= 1) s += __shfl_xor_sync(0xffffffffu, s, o);
    const float inv = 1.f / s;

    // group maxima + top-4 groups (exact, with margin)
    float gm[8];
#pragma unroll
    for (int j = 0; j < 8; j++) {
        float g = v[j];
#pragma unroll
        for (int o = 16; o; o >>= 1) g = fmaxf(g, __shfl_xor_sync(0xffffffffu, g, o));
        gm[j] = g;
    }
    unsigned keep = 0;
    float gv4 = 0.f, gv5 = 0.f;
#pragma unroll
    for (int r = 0; r < 5; r++) {
        int best = -1; float bv = -FLT_MAX;
#pragma unroll
        for (int g = 0; g < 8; g++) {
            if (keep & (1u << g)) continue;
            if (gm[g] > bv) { bv = gm[g]; best = g; }
        }
        if (r < 4) keep |= 1u << best;
        if (r == 3) gv4 = bv;
        if (r == 4) gv5 = bv;
    }
    bool risky = (gv4 - gv5 < TAU_G);

    // packed keys
    uint32_t kv[8];
#pragma unroll
    for (int j = 0; j < 8; j++) {
        uint32_t bits = __float_as_uint(e[j]) & 0xFFFFFF00u;
        kv[j] = ((keep >> j) & 1u) ? (bits | (255u - (unsigned)(j * 32 + lane))) : 0u;
    }

    float prev_f = 0.f;
#pragma unroll
    for (int r = 0; r < 9; r++) {
        uint32_t wk = kv[0];
#pragma unroll
        for (int j = 1; j < 8; j++) wk = max(wk, kv[j]);
#pragma unroll
        for (int o = 16; o; o >>= 1) wk = max(wk, __shfl_xor_sync(0xffffffffu, wk, o));
        float bv_f = __uint_as_float(wk & 0xFFFFFF00u);
        int idx = 255 - (int)(wk & 255u);
        if (r > 0 && (prev_f - bv_f < TAU_RANK * prev_f)) risky = true;
        prev_f = bv_f;
        if (r < 8) {
            if (lane == r) {
                wout[(size_t)warp * TOPK + r] = bv_f * inv;
                if (two_out) iout[(size_t)warp * TOPK + r] = (float)idx;
            }
            int jj = idx >> 5, ll = idx & 31;
            if (lane == ll) {
#pragma unroll
                for (int j = 0; j < 8; j++)
                    if (j == jj) kv[j] = 0u;
            }
        }
    }

    if (risky && lane == 0) {
        int pos = atomicAdd(&g_risky_count, 1);
        g_risky[pos] = warp;
    }
}

// ---------------------------------------------------------------------------
// Repair v6: two tokens per CTA, dual interleaved exact ascending-k fmaf
// chains (ILP=2 fills the 4-cyc FMA RAW slots; W smem ring shared).
// 4-stage cp.async ring, per-thread columns (no barriers in the chain).
// ---------------------------------------------------------------------------
#define RB      8                      // k4 per block
#define RNB     ((DIMD / 4) / RB)      // 128 blocks
#define RSTG    4
// dynamic smem: sx float4[2][1024] | sw float4[RSTG*RB*256] | slog float[2][256]
#define RSM_SX    0
#define RSM_SW    (2 * 1024 * 16)
#define RSM_SLOG  (RSM_SW + RSTG * RB * 256 * 16)
#define RSM_SIZE  (RSM_SLOG + 2 * 256 * 4)   // 164 KB

__global__ void __launch_bounds__(256)
repair_kernel(const float* __restrict__ X,
              float* __restrict__ wout, float* __restrict__ iout, int two_out)
{
    extern __shared__ char rsm[];
    float4* sx   = (float4*)(rsm + RSM_SX);          // [2][1024]
    float*  slog = (float*)(rsm + RSM_SLOG);         // [2][256]
    const uint32_t swb = smem_u32(rsm + RSM_SW);

    const int cnt = g_risky_count;
    const int e   = threadIdx.x;

    auto cpW = [&](int kb, int s) {
        const float4* src = g_wq + (size_t)kb * RB * NEXP + e;
        uint32_t dst = swb + ((s * RB) * 256 + e) * 16;
#pragma unroll
        for (int u = 0; u < RB; u++)
            cpasync16(dst + u * 256 * 16, src + (size_t)u * NEXP);
        asm volatile("cp.async.commit_group;" ::: "memory");
    };

    for (int pi = blockIdx.x; pi * 2 < cnt; pi += gridDim.x) {
        const int tokA = g_risky[pi * 2];
        const int has2 = (pi * 2 + 1 < cnt);
        const int tokB = has2 ? g_risky[pi * 2 + 1] : tokA;

        const float4* xa = (const float4*)(X + (size_t)tokA * DIMD);
        const float4* xb = (const float4*)(X + (size_t)tokB * DIMD);
#pragma unroll
        for (int u = 0; u < 4; u++) {
            sx[e + u * 256]        = xa[e + u * 256];
            sx[1024 + e + u * 256] = xb[e + u * 256];
        }
        __syncthreads();

        cpW(0, 0);
        cpW(1, 1);
        cpW(2, 2);

        float aA = 0.f, aB = 0.f;
        for (int kb = 0; kb < RNB; kb++) {
            const int s = kb & 3;
            if (kb + 3 < RNB) {
                cpW(kb + 3, (kb + 3) & 3);
                asm volatile("cp.async.wait_group 3;" ::: "memory");
            } else if (kb + 2 < RNB) {
                asm volatile("cp.async.wait_group 2;" ::: "memory");
            } else if (kb + 1 < RNB) {
                asm volatile("cp.async.wait_group 1;" ::: "memory");
            } else {
                asm volatile("cp.async.wait_group 0;" ::: "memory");
            }
            const float4* wblk = (float4*)(rsm + RSM_SW) + (s * RB) * 256 + e;
            const float4* xblkA = sx + kb * RB;
            const float4* xblkB = sx + 1024 + kb * RB;
#pragma unroll
            for (int u = 0; u < RB; u++) {
                float4 w  = wblk[u * 256];
                float4 x0 = xblkA[u];
                float4 x1 = xblkB[u];
                aA = fmaf(x0.x, w.x, aA);  aB = fmaf(x1.x, w.x, aB);
                aA = fmaf(x0.y, w.y, aA);  aB = fmaf(x1.y, w.y, aB);
                aA = fmaf(x0.z, w.z, aA);  aB = fmaf(x1.z, w.z, aB);
                aA = fmaf(x0.w, w.w, aA);  aB = fmaf(x1.w, w.w, aB);
                // each chain strictly ascending k == R1 chain
            }
        }

        slog[e]       = aA;
        slog[256 + e] = aB;
        __syncthreads();
        const int wid  = e >> 5;
        const int lane = e & 31;
        if (wid == 0) {
            float v[8];
#pragma unroll
            for (int j = 0; j < 8; j++) v[j] = slog[j * 32 + lane];
            route_exact(v, lane, tokA, wout, iout, two_out);
        } else if (wid == 1 && has2) {
            float v[8];
#pragma unroll
            for (int j = 0; j < 8; j++) v[j] = slog[256 + j * 32 + lane];
            route_exact(v, lane, tokB, wout, iout, two_out);
        }
        __syncthreads();   // protect slog/sx before next pair
    }
}

// ---------------------------------------------------------------------------
extern "C" void kernel_launch(void* const* d_in, const int* in_sizes, int n_in,
                              void* d_out, int out_size)
{
    const float* X = (const float*)d_in[0];
    const float* W = (const float*)d_in[1];
    const int T = in_sizes[0] / DIMD;   // 16384

    prep_w_kernel<<<1024, 256>>>(W);

    cudaFuncSetAttribute(gate_gemm_f16, cudaFuncAttributeMaxDynamicSharedMemorySize, SM_TOTAL);
    dim3 ggrid(NEXP / 128, T / 128);   // (2, 128) = 256 CTAs, 128x128 tiles
    gate_gemm_f16<<<ggrid, 256, SM_TOTAL>>>(X);

    float* wout = (float*)d_out;
    int two_out = (out_size >= 2 * T * TOPK) ? 1 : 0;
    float* iout = wout + (size_t)T * TOPK;
    gate_route_kernel<<<(T * 32 + 255) / 256, 256>>>(wout, iout, T, two_out);

    cudaFuncSetAttribute(repair_kernel, cudaFuncAttributeMaxDynamicSharedMemorySize, RSM_SIZE);
    repair_kernel<<<256, 256, RSM_SIZE>>>(X, wout, iout, two_out);
}